// round 11
// baseline (speedup 1.0000x reference)
#include <cuda_runtime.h>

// out[b, s, d] = in[b, s, d] + PE[s, d]
// PE[s, 2i]   = sin(s / 10000^(2i/1024)),  PE[s, 2i+1] = cos(...)
//
// B=8, S=4096, D=1024, fp32 — 268 MB pure stream, DRAM-bound (~74%).
// R11: (a) fast sincos — explicit 2-term Cody-Waite reduction mod 2pi
// (HI=6.28125 exact + MID fp32; k<=652 -> reduction err ~7e-8) followed by
// __sincosf on [-pi,pi] (MUFU, ~4e-7 abs err). ~5x cheaper than accurate
// sincosf. (b) That makes the next granularity halving affordable:
// BSPLIT=8 -> 1 batch per CTA, 32768 CTAs, minimal tail-drain quantum
// (R9/R10 showed each halving of CTA quantum improves wall time).
// Rejected: L2 policy pinning (R3-5), 256-bit ops (R6), persistent (R7).

#define SEQ_LEN 4096
#define D_MODEL 1024
#define BATCH   8
#define THREADS 256                    // 256 x float4 = one PE row

__device__ __forceinline__ void fast_sincos(float ang, float* s, float* c) {
    // 2-term Cody-Waite: 2pi = HI + MID, HI exact in fp32 (few mantissa bits)
    const float INV_2PI = 0.15915494309189535f;
    const float HI = 6.28125f;                 // exact
    const float MID = 1.9353071795864769e-3f;  // 2pi - HI
    float k = rintf(ang * INV_2PI);
    float r = fmaf(k, -HI, ang);
    r = fmaf(k, -MID, r);
    __sincosf(r, s, c);                        // |r| <= pi: MUFU-accurate
}

__global__ void __launch_bounds__(THREADS, 8)
pe_add_kernel(const float4* __restrict__ in, float4* __restrict__ out) {
    const int pos = blockIdx.x;        // sequence position 0..4095
    const int b   = blockIdx.y;        // batch 0..7
    const int t   = threadIdx.x;       // float4 index within row 0..255

    const float LOG2_10000 = 13.287712379549449f;
    const float fpos = (float)pos;

    // Angles for this thread's float4 (dims 4t..4t+3 = pairs 2t, 2t+1).
    float e0 = (float)(4 * t)     * (1.0f / 1024.0f);
    float e1 = (float)(4 * t + 2) * (1.0f / 1024.0f);
    float a0 = fpos / exp2f(e0 * LOG2_10000);
    float a1 = fpos / exp2f(e1 * LOG2_10000);

    float s0, c0, s1, c1;
    fast_sincos(a0, &s0, &c0);
    fast_sincos(a1, &s1, &c1);

    // 32-bit element offsets in float4 units.
    const int row_f4       = D_MODEL / 4;            // 256
    const int batch_stride = SEQ_LEN * row_f4;       // 1,048,576
    const int idx = b * batch_stride + pos * row_f4 + t;

    float4 v = __ldcs(in + idx);
    v.x += s0;
    v.y += c0;
    v.z += s1;
    v.w += c1;
    __stcs(out + idx, v);
}

extern "C" void kernel_launch(void* const* d_in, const int* in_sizes, int n_in,
                              void* d_out, int out_size) {
    const float4* in  = (const float4*)d_in[0];
    float4*       out = (float4*)d_out;
    dim3 grid(SEQ_LEN, BATCH);
    pe_add_kernel<<<grid, THREADS>>>(in, out);
}

// round 12
// speedup vs baseline: 1.0461x; 1.0461x over previous
#include <cuda_runtime.h>

// out[b, s, d] = in[b, s, d] + PE[s, d]
// PE[s, 2i]   = sin(s / 10000^(2i/1024)),  PE[s, 2i+1] = cos(...)
//
// B=8, S=4096, D=1024, fp32 — 268 MB pure stream, DRAM-bound (~74%).
// R12 = R10 geometry + R11 fast sincos.
//  - Granularity U-curve measured: 8 b/CTA 45.2 | 4 b/CTA 44.3 | 2 b/CTA
//    43.5 (best) | 1 b/CTA 45.8 (prologue unamortized, MLP=1). Use 2 b/CTA.
//  - fast_sincos: 2-term Cody-Waite mod 2pi (HI=6.28125 exact + MID;
//    k<=652 -> reduction err ~7e-8) + __sincosf MUFU on [-pi,pi].
//    Validated R11: rel_err 1.898e-5, identical to accurate sincosf.
//    Cuts the per-CTA prologue ~5x (fma 19% -> ~10%).
// Rejected: L2 policy pinning (R3-5), 256-bit ops (R6), persistent (R7),
// 1 batch/CTA (R11).

#define SEQ_LEN 4096
#define D_MODEL 1024
#define BATCH   8
#define BSPLIT  4                      // batch quarters per position
#define BPER    (BATCH / BSPLIT)       // 2 batches per CTA
#define THREADS 256                    // 256 x float4 = one PE row

__device__ __forceinline__ void fast_sincos(float ang, float* s, float* c) {
    // 2-term Cody-Waite: 2pi = HI + MID, HI exact in fp32.
    const float INV_2PI = 0.15915494309189535f;
    const float HI = 6.28125f;                 // exact
    const float MID = 1.9353071795864769e-3f;  // 2pi - HI
    float k = rintf(ang * INV_2PI);
    float r = fmaf(k, -HI, ang);
    r = fmaf(k, -MID, r);
    __sincosf(r, s, c);                        // |r| <= pi: MUFU-accurate
}

__global__ void __launch_bounds__(THREADS, 8)
pe_add_kernel(const float4* __restrict__ in, float4* __restrict__ out) {
    const int pos  = blockIdx.x;       // sequence position 0..4095
    const int bseg = blockIdx.y;       // batch segment 0..3
    const int t    = threadIdx.x;      // float4 index within row 0..255

    // 32-bit element offsets in float4 units.
    const int row_f4       = D_MODEL / 4;            // 256
    const int batch_stride = SEQ_LEN * row_f4;       // 1,048,576
    int idx = (bseg * BPER) * batch_stride + pos * row_f4 + t;

    // Kick the first load before the trig prologue.
    float4 cur = __ldcs(in + idx);

    // PE for this thread's float4 (dims 4t..4t+3), computed once, reused 2x.
    const float LOG2_10000 = 13.287712379549449f;
    const float fpos = (float)pos;

    float e0 = (float)(4 * t)     * (1.0f / 1024.0f);
    float e1 = (float)(4 * t + 2) * (1.0f / 1024.0f);
    float a0 = fpos / exp2f(e0 * LOG2_10000);
    float a1 = fpos / exp2f(e1 * LOG2_10000);

    float s0, c0, s1, c1;
    fast_sincos(a0, &s0, &c0);
    fast_sincos(a1, &s1, &c1);

    const float4 pe = make_float4(s0, c0, s1, c1);

    // 2-deep pipeline over this CTA's 2 batches.
#pragma unroll
    for (int b = 0; b < BPER; ++b) {
        int next_idx = idx + batch_stride;
        float4 nxt;
        if (b < BPER - 1) nxt = __ldcs(in + next_idx);
        float4 v = cur;
        v.x += pe.x;
        v.y += pe.y;
        v.z += pe.z;
        v.w += pe.w;
        __stcs(out + idx, v);
        cur = nxt;
        idx = next_idx;
    }
}

extern "C" void kernel_launch(void* const* d_in, const int* in_sizes, int n_in,
                              void* d_out, int out_size) {
    const float4* in  = (const float4*)d_in[0];
    float4*       out = (float4*)d_out;
    dim3 grid(SEQ_LEN, BSPLIT);
    pe_add_kernel<<<grid, THREADS>>>(in, out);
}